// round 1
// baseline (speedup 1.0000x reference)
#include <cuda_runtime.h>
#include <cuda_fp16.h>
#include <cstdint>

#define N_PTS 16384
#define C_DIM 64
#define D_REF 5
#define TI 128
#define TJ 64
#define LDA 72   // halves per row of score tile (144B, conflict-free for ldmatrix)
#define LDB 72

// Scratch (allocation-free per harness rules)
__device__ float  g_packed[N_PTS * 8];        // [sqrt(L2E)*r0..r4, -0.5*L2E*|r|^2, 0, 0]
__device__ __half g_Uh[N_PTS * C_DIM];        // U in fp16

__global__ void pack_kernel(const float* __restrict__ ref) {
    int p = blockIdx.x * blockDim.x + threadIdx.x;
    if (p >= N_PTS) return;
    float r0 = ref[p*5+0], r1 = ref[p*5+1], r2 = ref[p*5+2],
          r3 = ref[p*5+3], r4 = ref[p*5+4];
    float sq = r0*r0 + r1*r1 + r2*r2 + r3*r3 + r4*r4;
    const float L2E = 1.4426950408889634f;
    const float S   = 1.2011224087864498f;  // sqrt(L2E)
    float4* o = (float4*)(g_packed + p*8);
    o[0] = make_float4(r0*S, r1*S, r2*S, r3*S);
    o[1] = make_float4(r4*S, -0.5f*L2E*sq, 0.f, 0.f);
}

__global__ void cvtU_kernel(const float* __restrict__ U) {
    int idx = blockIdx.x * blockDim.x + threadIdx.x;
    if (idx >= N_PTS * C_DIM / 2) return;
    float2 v = ((const float2*)U)[idx];
    ((__half2*)g_Uh)[idx] = __floats2half2_rn(v.x, v.y);
}

__device__ __forceinline__ float ex2f(float x) {
    float r; asm("ex2.approx.f32 %0, %1;" : "=f"(r) : "f"(x)); return r;
}

__global__ void __launch_bounds__(256, 1)
lsh_main(const float* __restrict__ U, float* __restrict__ out) {
    __shared__ __align__(16) __half  sA[TI * LDA];  // score tile (fp16)
    __shared__ __align__(16) __half  sB[TJ * LDB];  // U tile (fp16)
    __shared__ __align__(16) float4  sRefI[TI * 2]; // packed ref for i-tile

    const int t    = threadIdx.x;
    const int lane = t & 31;
    const int w    = t >> 5;          // warp id 0..7
    const int i0   = blockIdx.x * TI;

    // preload i-side packed features (256 float4 = TI*2)
    sRefI[t] = ((const float4*)(g_packed + (size_t)i0 * 8))[t];

    float acc[8][4];
    #pragma unroll
    for (int f = 0; f < 8; f++)
        #pragma unroll
        for (int q = 0; q < 4; q++) acc[f][q] = 0.f;

    for (int j0 = 0; j0 < N_PTS; j0 += TJ) {
        // this thread's two j-points (cols 2*lane, 2*lane+1), straight from L2
        const float4* pj = (const float4*)(g_packed + (size_t)(j0 + 2*lane) * 8);
        float4 ja0 = pj[0], jb0 = pj[1], ja1 = pj[2], jb1 = pj[3];

        __syncthreads();  // prev-iter mma done reading sA/sB; iter0: sRefI visible

        // ---- copy U fp16 tile into sB (64 rows x 64 halves) ----
        #pragma unroll
        for (int kidx = 0; kidx < 2; kidx++) {
            int idx = t + 256 * kidx;
            int row = idx >> 3, c8 = idx & 7;
            uint4 v = ((const uint4*)(g_Uh + (size_t)(j0 + row) * C_DIM))[c8];
            ((uint4*)(sB + row * LDB))[c8] = v;
        }

        // ---- scores: w = 2^min(ri'.rj' + hi + hj, 0) ----
        #pragma unroll
        for (int s = 0; s < 16; s++) {
            int i = w + 8 * s;                 // each warp: rows w, w+8, ..., w+120
            float4 ia = sRefI[2*i];            // broadcast within warp
            float4 ib = sRefI[2*i + 1];
            float hli = ib.y;

            float e0 = hli + jb0.y;
            e0 = fmaf(ia.x, ja0.x, e0);
            e0 = fmaf(ia.y, ja0.y, e0);
            e0 = fmaf(ia.z, ja0.z, e0);
            e0 = fmaf(ia.w, ja0.w, e0);
            e0 = fmaf(ib.x, jb0.x, e0);

            float e1 = hli + jb1.y;
            e1 = fmaf(ia.x, ja1.x, e1);
            e1 = fmaf(ia.y, ja1.y, e1);
            e1 = fmaf(ia.z, ja1.z, e1);
            e1 = fmaf(ia.w, ja1.w, e1);
            e1 = fmaf(ib.x, jb1.x, e1);

            e0 = fminf(e0, 0.f);
            e1 = fminf(e1, 0.f);
            float w0 = ex2f(e0);
            float w1 = ex2f(e1);
            // lane-consecutive half2 store: conflict-free
            ((__half2*)(sA + i * LDA))[lane] = __floats2half2_rn(w0, w1);
        }

        __syncthreads();

        // ---- K_tile @ U_tile via mma.m16n8k16 ----
        const __half* Abase = sA + (w * 16) * LDA;
        #pragma unroll
        for (int kk = 0; kk < TJ; kk += 16) {
            uint32_t a0, a1, a2, a3;
            uint32_t aaddr = (uint32_t)__cvta_generic_to_shared(
                Abase + (lane & 15) * LDA + kk + (lane >> 4) * 8);
            asm volatile("ldmatrix.sync.aligned.m8n8.x4.shared.b16 {%0,%1,%2,%3}, [%4];"
                         : "=r"(a0), "=r"(a1), "=r"(a2), "=r"(a3) : "r"(aaddr));
            #pragma unroll
            for (int nb = 0; nb < 4; nb++) {
                int n0 = nb * 16;
                uint32_t b0, b1, b2, b3;
                uint32_t baddr = (uint32_t)__cvta_generic_to_shared(
                    sB + (kk + (lane & 15)) * LDB + n0 + (lane >> 4) * 8);
                asm volatile("ldmatrix.sync.aligned.m8n8.x4.trans.shared.b16 {%0,%1,%2,%3}, [%4];"
                             : "=r"(b0), "=r"(b1), "=r"(b2), "=r"(b3) : "r"(baddr));
                asm volatile("mma.sync.aligned.m16n8k16.row.col.f32.f16.f16.f32 "
                             "{%0,%1,%2,%3}, {%4,%5,%6,%7}, {%8,%9}, {%0,%1,%2,%3};"
                             : "+f"(acc[2*nb][0]), "+f"(acc[2*nb][1]),
                               "+f"(acc[2*nb][2]), "+f"(acc[2*nb][3])
                             : "r"(a0), "r"(a1), "r"(a2), "r"(a3), "r"(b0), "r"(b1));
                asm volatile("mma.sync.aligned.m16n8k16.row.col.f32.f16.f16.f32 "
                             "{%0,%1,%2,%3}, {%4,%5,%6,%7}, {%8,%9}, {%0,%1,%2,%3};"
                             : "+f"(acc[2*nb+1][0]), "+f"(acc[2*nb+1][1]),
                               "+f"(acc[2*nb+1][2]), "+f"(acc[2*nb+1][3])
                             : "r"(a0), "r"(a1), "r"(a2), "r"(a3), "r"(b2), "r"(b3));
            }
        }
    }

    // ---- epilogue: out = acc - U ----
    #pragma unroll
    for (int f = 0; f < 8; f++) {
        int col  = f * 8 + (lane & 3) * 2;
        int row  = i0 + w * 16 + (lane >> 2);
        float2 u0 = *(const float2*)(U + (size_t)row * C_DIM + col);
        *(float2*)(out + (size_t)row * C_DIM + col) =
            make_float2(acc[f][0] - u0.x, acc[f][1] - u0.y);
        int row2 = row + 8;
        float2 u1 = *(const float2*)(U + (size_t)row2 * C_DIM + col);
        *(float2*)(out + (size_t)row2 * C_DIM + col) =
            make_float2(acc[f][2] - u1.x, acc[f][3] - u1.y);
    }
}

extern "C" void kernel_launch(void* const* d_in, const int* in_sizes, int n_in,
                              void* d_out, int out_size) {
    const float* U   = (const float*)d_in[0];
    const float* ref = (const float*)d_in[1];
    if (n_in >= 2 && in_sizes[0] == N_PTS * D_REF) {  // defensive: metadata order
        U = (const float*)d_in[1];
        ref = (const float*)d_in[0];
    }
    pack_kernel<<<(N_PTS + 255) / 256, 256>>>(ref);
    cvtU_kernel<<<(N_PTS * C_DIM / 2 + 255) / 256, 256>>>(U);
    lsh_main<<<N_PTS / TI, 256>>>(U, (float*)d_out);
}

// round 5
// speedup vs baseline: 1.3194x; 1.3194x over previous
#include <cuda_runtime.h>
#include <cuda_fp16.h>
#include <cstdint>

#define N_PTS 16384
#define C_DIM 64
#define TI 64
#define TJ 64
#define LDA 72   // halves per sA row
#define LDB 72   // halves per sB row
#define NITERS (N_PTS / TJ)

typedef unsigned long long ull;

// ---------------- scratch (no allocs allowed) ----------------
__device__ float  g_iside[N_PTS * 6];          // per point: 5 scaled comps + h
__device__ ull    g_jpairs[(N_PTS / 2) * 6];   // per pair: {c0a,c0b}..{c4a,c4b},{ha,hb}
__device__ __half g_Uh[N_PTS * C_DIM];         // U fp16 row-major

// ---------------- helpers ----------------
__device__ __forceinline__ ull fma2(ull a, ull b, ull c) {
    ull d; asm("fma.rn.f32x2 %0, %1, %2, %3;" : "=l"(d) : "l"(a), "l"(b), "l"(c)); return d;
}
__device__ __forceinline__ ull add2(ull a, ull b) {
    ull d; asm("add.rn.f32x2 %0, %1, %2;" : "=l"(d) : "l"(a), "l"(b)); return d;
}
__device__ __forceinline__ float ex2f(float x) {
    float r; asm("ex2.approx.f32 %0, %1;" : "=f"(r) : "f"(x)); return r;
}

// ---------------- prep kernels ----------------
__global__ void prep_kernel(const float* __restrict__ ref) {
    int q = blockIdx.x * blockDim.x + threadIdx.x;
    if (q >= N_PTS / 2) return;
    const float L2E = 1.4426950408889634f;
    const float S   = 1.2011224087864498f;  // sqrt(log2 e)
    float a[5], b[5], sa = 0.f, sb = 0.f;
    #pragma unroll
    for (int c = 0; c < 5; c++) { a[c] = ref[(2 * q) * 5 + c];     sa += a[c] * a[c]; }
    #pragma unroll
    for (int c = 0; c < 5; c++) { b[c] = ref[(2 * q + 1) * 5 + c]; sb += b[c] * b[c]; }
    float ha = -0.5f * L2E * sa, hb = -0.5f * L2E * sb;
    float* jp = (float*)(g_jpairs + (size_t)q * 6);
    #pragma unroll
    for (int c = 0; c < 5; c++) { jp[2 * c] = a[c] * S; jp[2 * c + 1] = b[c] * S; }
    jp[10] = ha; jp[11] = hb;
    float* ia = g_iside + (size_t)(2 * q) * 6;
    float* ib = g_iside + (size_t)(2 * q + 1) * 6;
    #pragma unroll
    for (int c = 0; c < 5; c++) { ia[c] = a[c] * S; ib[c] = b[c] * S; }
    ia[5] = ha; ib[5] = hb;
}

__global__ void cvtU_kernel(const float* __restrict__ U) {
    int idx = blockIdx.x * blockDim.x + threadIdx.x;
    if (idx >= N_PTS * C_DIM / 2) return;
    float2 v = ((const float2*)U)[idx];
    ((__half2*)g_Uh)[idx] = __floats2half2_rn(v.x, v.y);
}

// ---------------- main kernel ----------------
__global__ void __launch_bounds__(256, 2)
lsh_main(const float* __restrict__ U, float* __restrict__ out) {
    __shared__ __align__(16) __half sA[2][TI * LDA];
    __shared__ __align__(16) __half sB[2][TJ * LDB];
    __shared__ __align__(16) ull    sRef[TI * 6];   // {v,v}-duplicated i-features

    const int tid  = threadIdx.x;
    const int lane = tid & 31;
    const int w    = tid >> 5;          // 0..7
    const int i0   = blockIdx.x * TI;

    // fill duplicated i-side features (64 rows x 6 ull)
    for (int idx = tid; idx < TI * 6; idx += 256) {
        float v = g_iside[(size_t)(i0 + idx / 6) * 6 + (idx % 6)];
        float2 d2 = make_float2(v, v);
        sRef[idx] = *(ull*)&d2;
    }

    float acc[4][4];
    #pragma unroll
    for (int f = 0; f < 4; f++)
        #pragma unroll
        for (int q = 0; q < 4; q++) acc[f][q] = 0.f;

    const int brow = tid >> 3, bchunk = tid & 7;   // B staging: idx,idx+256
    const int mw = w & 3;                          // mma m-tile
    const int nh = w >> 2;                         // mma n-half (0/1)

    // ---- produce tile `it` into buffer `buf` ----
    auto produce = [&](int it, int buf) {
        const int j0 = it * TJ;
        // B tile: 64 rows x 64 halves (two 16B chunks per thread)
        #pragma unroll
        for (int p = 0; p < 2; p++) {
            int idx = tid + 256 * p;
            int row = idx >> 3, c8 = idx & 7;
            ((uint4*)(sB[buf] + row * LDB))[c8] =
                ((const uint4*)(g_Uh + (size_t)(j0 + row) * C_DIM))[c8];
        }
        // j-pair features for this lane (2 columns: 2*lane, 2*lane+1)
        const ulonglong2* jp2 = (const ulonglong2*)(g_jpairs + (size_t)(j0 / 2 + lane) * 6);
        ulonglong2 p0 = jp2[0], p1 = jp2[1], p2 = jp2[2];
        // scores: 8 rows per warp
        #pragma unroll
        for (int s = 0; s < 8; s++) {
            const int i = w * 8 + s;
            const ulonglong2* R = (const ulonglong2*)(sRef + i * 6);
            ulonglong2 r0 = R[0], r1 = R[1], r2 = R[2];
            ull e = add2(r2.y, p2.y);           // {hi,hi} + {ha,hb}
            e = fma2(r0.x, p0.x, e);
            e = fma2(r0.y, p0.y, e);
            e = fma2(r1.x, p1.x, e);
            e = fma2(r1.y, p1.y, e);
            e = fma2(r2.x, p2.x, e);
            float e0, e1;
            asm("mov.b64 {%0, %1}, %2;" : "=f"(e0), "=f"(e1) : "l"(e));
            e0 = fminf(e0, 0.f); e1 = fminf(e1, 0.f);
            float w0 = ex2f(e0), w1 = ex2f(e1);
            ((__half2*)(sA[buf] + i * LDA))[lane] = __floats2half2_rn(w0, w1);
        }
    };

    // ---- consume buffer `buf` (K_tile @ U_tile) ----
    auto consume = [&](int buf) {
        const __half* Abase = sA[buf] + (mw * 16) * LDA;
        #pragma unroll
        for (int kk = 0; kk < TJ; kk += 16) {
            uint32_t a0, a1, a2, a3;
            uint32_t aaddr = (uint32_t)__cvta_generic_to_shared(
                Abase + (lane & 15) * LDA + kk + (lane >> 4) * 8);
            asm volatile("ldmatrix.sync.aligned.m8n8.x4.shared.b16 {%0,%1,%2,%3}, [%4];"
                         : "=r"(a0), "=r"(a1), "=r"(a2), "=r"(a3) : "r"(aaddr));
            #pragma unroll
            for (int nb = 0; nb < 2; nb++) {
                int n0 = nh * 32 + nb * 16;
                uint32_t b0, b1, b2, b3;
                uint32_t baddr = (uint32_t)__cvta_generic_to_shared(
                    sB[buf] + (kk + (lane & 15)) * LDB + n0 + (lane >> 4) * 8);
                asm volatile("ldmatrix.sync.aligned.m8n8.x4.trans.shared.b16 {%0,%1,%2,%3}, [%4];"
                             : "=r"(b0), "=r"(b1), "=r"(b2), "=r"(b3) : "r"(baddr));
                asm volatile("mma.sync.aligned.m16n8k16.row.col.f32.f16.f16.f32 "
                             "{%0,%1,%2,%3}, {%4,%5,%6,%7}, {%8,%9}, {%0,%1,%2,%3};"
                             : "+f"(acc[2*nb][0]), "+f"(acc[2*nb][1]),
                               "+f"(acc[2*nb][2]), "+f"(acc[2*nb][3])
                             : "r"(a0), "r"(a1), "r"(a2), "r"(a3), "r"(b0), "r"(b1));
                asm volatile("mma.sync.aligned.m16n8k16.row.col.f32.f16.f16.f32 "
                             "{%0,%1,%2,%3}, {%4,%5,%6,%7}, {%8,%9}, {%0,%1,%2,%3};"
                             : "+f"(acc[2*nb+1][0]), "+f"(acc[2*nb+1][1]),
                               "+f"(acc[2*nb+1][2]), "+f"(acc[2*nb+1][3])
                             : "r"(a0), "r"(a1), "r"(a2), "r"(a3), "r"(b2), "r"(b3));
            }
        }
    };

    __syncthreads();          // sRef visible
    produce(0, 0);
    __syncthreads();

    for (int it = 0; it < NITERS; ++it) {
        const int cur = it & 1;
        if (it + 1 < NITERS) produce(it + 1, cur ^ 1);
        consume(cur);
        __syncthreads();      // consume(cur) done before cur is overwritten next iter
    }

    // ---- epilogue: out = acc - U ----
    #pragma unroll
    for (int f = 0; f < 4; f++) {
        int col = nh * 32 + f * 8 + (lane & 3) * 2;
        int row = i0 + mw * 16 + (lane >> 2);
        float2 u0 = *(const float2*)(U + (size_t)row * C_DIM + col);
        *(float2*)(out + (size_t)row * C_DIM + col) =
            make_float2(acc[f][0] - u0.x, acc[f][1] - u0.y);
        int row2 = row + 8;
        float2 u1 = *(const float2*)(U + (size_t)row2 * C_DIM + col);
        *(float2*)(out + (size_t)row2 * C_DIM + col) =
            make_float2(acc[f][2] - u1.x, acc[f][3] - u1.y);
    }
}

extern "C" void kernel_launch(void* const* d_in, const int* in_sizes, int n_in,
                              void* d_out, int out_size) {
    const float* U   = (const float*)d_in[0];
    const float* ref = (const float*)d_in[1];
    if (n_in >= 2 && in_sizes[0] == N_PTS * 5) {  // defensive metadata-order check
        U = (const float*)d_in[1];
        ref = (const float*)d_in[0];
    }
    prep_kernel<<<(N_PTS / 2 + 255) / 256, 256>>>(ref);
    cvtU_kernel<<<(N_PTS * C_DIM / 2 + 255) / 256, 256>>>(U);
    lsh_main<<<N_PTS / TI, 256>>>(U, (float*)d_out);
}

// round 6
// speedup vs baseline: 2.1880x; 1.6583x over previous
#include <cuda_runtime.h>
#include <cuda_fp16.h>
#include <cstdint>

#define N_PTS 16384
#define C_DIM 64
#define TI 64
#define TJ 64
#define LDA 72   // halves per sA row
#define LDB 72   // halves per sB row
#define NITERS (N_PTS / TJ)

// ---------------- scratch (no allocs allowed) ----------------
__device__ uint32_t g_iext[N_PTS * 8];   // A-side feats [r0..r4,1,0,0] (tf32 bits)
__device__ float    g_h[N_PTS];          // exact fp32 h_i
__device__ float2   g_jext2[N_PTS * 4];  // B-side pairs {(f0,f4),(f1,h),(f2,0),(f3,0)} tf32
__device__ __half   g_Uh[N_PTS * C_DIM]; // U fp16 row-major

__device__ __forceinline__ uint32_t tf32r(float v) {
    uint32_t u; asm("cvt.rna.tf32.f32 %0, %1;" : "=r"(u) : "f"(v)); return u;
}

// ---------------- fused prep: features + U->fp16 ----------------
__global__ void prep_kernel(const float* __restrict__ ref, const float* __restrict__ U) {
    int p = blockIdx.x * blockDim.x + threadIdx.x;
    if (p < N_PTS) {
        const float L2E = 1.4426950408889634f;
        const float S   = 1.2011224087864498f;   // sqrt(log2 e)
        float r[5]; float sq = 0.f;
        #pragma unroll
        for (int c = 0; c < 5; c++) { r[c] = ref[p * 5 + c]; sq += r[c] * r[c]; }
        float h = -0.5f * L2E * sq;
        uint32_t f[6];
        #pragma unroll
        for (int c = 0; c < 5; c++) f[c] = tf32r(r[c] * S);
        f[5] = tf32r(h);
        uint32_t* ie = g_iext + (size_t)p * 8;
        ie[0] = f[0]; ie[1] = f[1]; ie[2] = f[2]; ie[3] = f[3]; ie[4] = f[4];
        ie[5] = tf32r(1.0f); ie[6] = 0u; ie[7] = 0u;
        g_h[p] = h;
        float2* je = g_jext2 + (size_t)p * 4;
        je[0] = make_float2(__uint_as_float(f[0]), __uint_as_float(f[4]));
        je[1] = make_float2(__uint_as_float(f[1]), __uint_as_float(f[5]));
        je[2] = make_float2(__uint_as_float(f[2]), 0.f);
        je[3] = make_float2(__uint_as_float(f[3]), 0.f);
    }
    // coalesced U -> fp16 (grid-stride)
    for (int idx = blockIdx.x * blockDim.x + threadIdx.x;
         idx < N_PTS * C_DIM / 2; idx += gridDim.x * blockDim.x) {
        float2 v = ((const float2*)U)[idx];
        ((__half2*)g_Uh)[idx] = __floats2half2_rn(v.x, v.y);
    }
}

// ---------------- main kernel ----------------
__global__ void __launch_bounds__(256, 2)
lsh_main(const float* __restrict__ U, float* __restrict__ out) {
    __shared__ __align__(16) __half sA[2][TI * LDA];
    __shared__ __align__(16) __half sB[2][TJ * LDB];

    const int tid  = threadIdx.x;
    const int lane = tid & 31;
    const int w    = tid >> 5;          // 0..7
    const int mw   = w & 3;             // m16 tile
    const int nh   = w >> 2;            // n32 half
    const int i0   = blockIdx.x * TI;
    const int qr   = lane >> 2;         // 0..7
    const int qc   = lane & 3;          // 0..3

    // per-thread i-side constants (A fragment for tf32 S-mma + exact h)
    const int ri = i0 + mw * 16 + qr;
    const float hlo = g_h[ri];
    const float hhi = g_h[ri + 8];
    const uint32_t ia0 = g_iext[(size_t)ri * 8 + qc];
    const uint32_t ia1 = g_iext[(size_t)(ri + 8) * 8 + qc];
    const uint32_t ia2 = g_iext[(size_t)ri * 8 + qc + 4];
    const uint32_t ia3 = g_iext[(size_t)(ri + 8) * 8 + qc + 4];

    float acc[4][4];
    #pragma unroll
    for (int f = 0; f < 4; f++)
        #pragma unroll
        for (int q = 0; q < 4; q++) acc[f][q] = 0.f;

    // ---- produce tile `it` into buffer `buf` ----
    auto produce = [&](int it, int buf) {
        const int j0 = it * TJ;
        // stage U tile (64 rows x 64 halves)
        #pragma unroll
        for (int p = 0; p < 2; p++) {
            int idx = tid + 256 * p;
            int row = idx >> 3, c8 = idx & 7;
            ((uint4*)(sB[buf] + row * LDB))[c8] =
                ((const uint4*)(g_Uh + (size_t)(j0 + row) * C_DIM))[c8];
        }
        // scores via tf32 mma: warp covers (m16 tile mw) x (j cols nh*32..+31)
        #pragma unroll
        for (int t = 0; t < 4; t++) {
            const int j = j0 + nh * 32 + t * 8 + qr;
            float2 bf = g_jext2[(size_t)j * 4 + qc];
            uint32_t b0 = __float_as_uint(bf.x), b1 = __float_as_uint(bf.y);
            float c0 = 0.f, c1 = 0.f, c2 = 0.f, c3 = 0.f;
            asm volatile("mma.sync.aligned.m16n8k8.row.col.f32.tf32.tf32.f32 "
                         "{%0,%1,%2,%3}, {%4,%5,%6,%7}, {%8,%9}, {%0,%1,%2,%3};"
                         : "+f"(c0), "+f"(c1), "+f"(c2), "+f"(c3)
                         : "r"(ia0), "r"(ia1), "r"(ia2), "r"(ia3), "r"(b0), "r"(b1));
            float e0 = fminf(c0 + hlo, 0.f), e1 = fminf(c1 + hlo, 0.f);
            float e2 = fminf(c2 + hhi, 0.f), e3 = fminf(c3 + hhi, 0.f);
            uint32_t plo, phi, wlo, whi;
            asm("cvt.rn.f16x2.f32 %0, %1, %2;" : "=r"(plo) : "f"(e1), "f"(e0)); // lo=e0
            asm("cvt.rn.f16x2.f32 %0, %1, %2;" : "=r"(phi) : "f"(e3), "f"(e2));
            asm("ex2.approx.f16x2 %0, %1;" : "=r"(wlo) : "r"(plo));
            asm("ex2.approx.f16x2 %0, %1;" : "=r"(whi) : "r"(phi));
            const int row = mw * 16 + qr;
            const int col = nh * 32 + t * 8 + 2 * qc;
            *(uint32_t*)(sA[buf] + row * LDA + col)       = wlo;
            *(uint32_t*)(sA[buf] + (row + 8) * LDA + col) = whi;
        }
    };

    // ---- consume buffer `buf` (K_tile @ U_tile) ----
    auto consume = [&](int buf) {
        const __half* Abase = sA[buf] + (mw * 16) * LDA;
        #pragma unroll
        for (int kk = 0; kk < TJ; kk += 16) {
            uint32_t a0, a1, a2, a3;
            uint32_t aaddr = (uint32_t)__cvta_generic_to_shared(
                Abase + (lane & 15) * LDA + kk + (lane >> 4) * 8);
            asm volatile("ldmatrix.sync.aligned.m8n8.x4.shared.b16 {%0,%1,%2,%3}, [%4];"
                         : "=r"(a0), "=r"(a1), "=r"(a2), "=r"(a3) : "r"(aaddr));
            #pragma unroll
            for (int nb = 0; nb < 2; nb++) {
                int n0 = nh * 32 + nb * 16;
                uint32_t b0, b1, b2, b3;
                uint32_t baddr = (uint32_t)__cvta_generic_to_shared(
                    sB[buf] + (kk + (lane & 15)) * LDB + n0 + (lane >> 4) * 8);
                asm volatile("ldmatrix.sync.aligned.m8n8.x4.trans.shared.b16 {%0,%1,%2,%3}, [%4];"
                             : "=r"(b0), "=r"(b1), "=r"(b2), "=r"(b3) : "r"(baddr));
                asm volatile("mma.sync.aligned.m16n8k16.row.col.f32.f16.f16.f32 "
                             "{%0,%1,%2,%3}, {%4,%5,%6,%7}, {%8,%9}, {%0,%1,%2,%3};"
                             : "+f"(acc[2*nb][0]), "+f"(acc[2*nb][1]),
                               "+f"(acc[2*nb][2]), "+f"(acc[2*nb][3])
                             : "r"(a0), "r"(a1), "r"(a2), "r"(a3), "r"(b0), "r"(b1));
                asm volatile("mma.sync.aligned.m16n8k16.row.col.f32.f16.f16.f32 "
                             "{%0,%1,%2,%3}, {%4,%5,%6,%7}, {%8,%9}, {%0,%1,%2,%3};"
                             : "+f"(acc[2*nb+1][0]), "+f"(acc[2*nb+1][1]),
                               "+f"(acc[2*nb+1][2]), "+f"(acc[2*nb+1][3])
                             : "r"(a0), "r"(a1), "r"(a2), "r"(a3), "r"(b2), "r"(b3));
            }
        }
    };

    produce(0, 0);
    __syncthreads();

    for (int it = 0; it < NITERS; ++it) {
        const int cur = it & 1;
        if (it + 1 < NITERS) produce(it + 1, cur ^ 1);
        consume(cur);
        __syncthreads();
    }

    // ---- epilogue: out = acc - U ----
    #pragma unroll
    for (int f = 0; f < 4; f++) {
        int col = nh * 32 + f * 8 + (lane & 3) * 2;
        int row = i0 + mw * 16 + (lane >> 2);
        float2 u0 = *(const float2*)(U + (size_t)row * C_DIM + col);
        *(float2*)(out + (size_t)row * C_DIM + col) =
            make_float2(acc[f][0] - u0.x, acc[f][1] - u0.y);
        int row2 = row + 8;
        float2 u1 = *(const float2*)(U + (size_t)row2 * C_DIM + col);
        *(float2*)(out + (size_t)row2 * C_DIM + col) =
            make_float2(acc[f][2] - u1.x, acc[f][3] - u1.y);
    }
}

extern "C" void kernel_launch(void* const* d_in, const int* in_sizes, int n_in,
                              void* d_out, int out_size) {
    const float* U   = (const float*)d_in[0];
    const float* ref = (const float*)d_in[1];
    if (n_in >= 2 && in_sizes[0] == N_PTS * 5) {  // defensive metadata-order check
        U = (const float*)d_in[1];
        ref = (const float*)d_in[0];
    }
    prep_kernel<<<N_PTS / 256, 256>>>(ref, U);
    lsh_main<<<N_PTS / TI, 256>>>(U, (float*)d_out);
}

// round 8
// speedup vs baseline: 2.4193x; 1.1057x over previous
#include <cuda_runtime.h>
#include <cuda_fp16.h>
#include <cstdint>

#define N_PTS 16384
#define C_DIM 64
#define NFRAG (N_PTS / 16 * 4 * 32)   // 131072 uint4 fragments

// ---------------- scratch (no allocs allowed) ----------------
__device__ uint32_t g_iext[N_PTS * 8];        // A-side feats [r0..r4,1,0,0] tf32 bits
__device__ float    g_h[N_PTS];               // exact fp32 h_i
__device__ float2   g_jext2[N_PTS * 4];       // score-mma B frags {(f0,f4),(f1,h),(f2,0),(f3,0)}
__device__ uint4    g_Ufrag[NFRAG];           // U fp16, HMMA-B fragment order
__device__ float    g_part[2 * N_PTS * C_DIM];// split-j partials

__device__ __forceinline__ uint32_t tf32r(float v) {
    uint32_t u; asm("cvt.rna.tf32.f32 %0, %1;" : "=r"(u) : "f"(v)); return u;
}

// ---------------- prep: bilateral features ----------------
__global__ void prep_kernel(const float* __restrict__ ref) {
    int p = blockIdx.x * blockDim.x + threadIdx.x;
    if (p >= N_PTS) return;
    const float L2E = 1.4426950408889634f;
    const float S   = 1.2011224087864498f;   // sqrt(log2 e)
    float r[5]; float sq = 0.f;
    #pragma unroll
    for (int c = 0; c < 5; c++) { r[c] = ref[p * 5 + c]; sq += r[c] * r[c]; }
    float h = -0.5f * L2E * sq;
    uint32_t f[6];
    #pragma unroll
    for (int c = 0; c < 5; c++) f[c] = tf32r(r[c] * S);
    f[5] = tf32r(h);
    uint32_t* ie = g_iext + (size_t)p * 8;
    ie[0] = f[0]; ie[1] = f[1]; ie[2] = f[2]; ie[3] = f[3]; ie[4] = f[4];
    ie[5] = tf32r(1.0f); ie[6] = 0u; ie[7] = 0u;
    g_h[p] = h;
    float2* je = g_jext2 + (size_t)p * 4;
    je[0] = make_float2(__uint_as_float(f[0]), __uint_as_float(f[4]));
    je[1] = make_float2(__uint_as_float(f[1]), __uint_as_float(f[5]));
    je[2] = make_float2(__uint_as_float(f[2]), 0.f);
    je[3] = make_float2(__uint_as_float(f[3]), 0.f);
}

// ---------------- prep: U -> fp16 HMMA-B fragment order ----------------
// frag idx = (J*4 + nbp)*32 + lane ; J = abs k16 block, nbp = n16 pair of n8 blocks
// uint4 = {b0(nb=2nbp), b1(2nbp), b0(2nbp+1), b1(2nbp+1)}
// b0 = half2{U[J16+2qc][c], U[J16+2qc+1][c]}, b1 = rows +8,+9 ; c = nb*8 + qr
__global__ void prepU_kernel(const float* __restrict__ U) {
    int idx = blockIdx.x * blockDim.x + threadIdx.x;
    if (idx >= NFRAG) return;
    int lane = idx & 31, nbp = (idx >> 5) & 3, J = idx >> 7;
    int qr = lane >> 2, qc = lane & 3;
    int j = J * 16 + 2 * qc;
    uint32_t rr[4];
    #pragma unroll
    for (int p = 0; p < 2; p++) {
        int c = (2 * nbp + p) * 8 + qr;
        float f0 = U[(size_t)j * C_DIM + c];
        float f1 = U[(size_t)(j + 1) * C_DIM + c];
        float f2 = U[(size_t)(j + 8) * C_DIM + c];
        float f3 = U[(size_t)(j + 9) * C_DIM + c];
        __half2 h0 = __floats2half2_rn(f0, f1);   // lo = row 2qc
        __half2 h1 = __floats2half2_rn(f2, f3);
        rr[2 * p]     = *(uint32_t*)&h0;
        rr[2 * p + 1] = *(uint32_t*)&h1;
    }
    g_Ufrag[idx] = make_uint4(rr[0], rr[1], rr[2], rr[3]);
}

// ---------------- main kernel: no smem, no barriers ----------------
__device__ __forceinline__ void score2(
    const uint32_t ia0, const uint32_t ia1, const uint32_t ia2, const uint32_t ia3,
    const float h0, const float h1, const float2 bf,
    uint32_t& w_lo, uint32_t& w_hi)
{
    uint32_t b0 = __float_as_uint(bf.x), b1 = __float_as_uint(bf.y);
    float c0 = 0.f, c1 = 0.f, c2 = 0.f, c3 = 0.f;
    asm volatile("mma.sync.aligned.m16n8k8.row.col.f32.tf32.tf32.f32 "
                 "{%0,%1,%2,%3}, {%4,%5,%6,%7}, {%8,%9}, {%0,%1,%2,%3};"
                 : "+f"(c0), "+f"(c1), "+f"(c2), "+f"(c3)
                 : "r"(ia0), "r"(ia1), "r"(ia2), "r"(ia3), "r"(b0), "r"(b1));
    float e0 = c0 + h0, e1 = c1 + h0, e2 = c2 + h1, e3 = c3 + h1;
    uint32_t plo, phi;
    asm("cvt.rn.f16x2.f32 %0, %1, %2;" : "=r"(plo) : "f"(e1), "f"(e0)); // lo=e0
    asm("cvt.rn.f16x2.f32 %0, %1, %2;" : "=r"(phi) : "f"(e3), "f"(e2));
    asm("min.f16x2 %0, %1, %2;" : "=r"(plo) : "r"(plo), "r"(0u));
    asm("min.f16x2 %0, %1, %2;" : "=r"(phi) : "r"(phi), "r"(0u));
    asm("ex2.approx.f16x2 %0, %1;" : "=r"(w_lo) : "r"(plo));
    asm("ex2.approx.f16x2 %0, %1;" : "=r"(w_hi) : "r"(phi));
}

#define HMMA(ACC, A0, A1, A2, A3, B0, B1) \
    asm volatile("mma.sync.aligned.m16n8k16.row.col.f32.f16.f16.f32 " \
                 "{%0,%1,%2,%3}, {%4,%5,%6,%7}, {%8,%9}, {%0,%1,%2,%3};" \
                 : "+f"(ACC[0]), "+f"(ACC[1]), "+f"(ACC[2]), "+f"(ACC[3]) \
                 : "r"(A0), "r"(A1), "r"(A2), "r"(A3), "r"(B0), "r"(B1))

__global__ void __launch_bounds__(64)
lsh_main(void) {
    const int lane = threadIdx.x & 31;
    const int w    = threadIdx.x >> 5;          // 0..1
    const int bid  = blockIdx.x;
    const int ib   = bid & 255;                 // i-tile
    const int jh   = bid >> 8;                  // j-half
    const int i0   = ib * 64;
    const int qr   = lane >> 2, qc = lane & 3;

    // two m16 tiles per warp: Upper rows riU(+8), Lower riL(+8)
    const int riU = i0 + w * 32 + qr;
    const int riL = riU + 16;
    const uint32_t iaU0 = g_iext[(size_t)riU * 8 + qc];
    const uint32_t iaU1 = g_iext[(size_t)(riU + 8) * 8 + qc];
    const uint32_t iaU2 = g_iext[(size_t)riU * 8 + qc + 4];
    const uint32_t iaU3 = g_iext[(size_t)(riU + 8) * 8 + qc + 4];
    const uint32_t iaL0 = g_iext[(size_t)riL * 8 + qc];
    const uint32_t iaL1 = g_iext[(size_t)(riL + 8) * 8 + qc];
    const uint32_t iaL2 = g_iext[(size_t)riL * 8 + qc + 4];
    const uint32_t iaL3 = g_iext[(size_t)(riL + 8) * 8 + qc + 4];
    const float hU0 = g_h[riU], hU1 = g_h[riU + 8];
    const float hL0 = g_h[riL], hL1 = g_h[riL + 8];

    float aU[8][4], aL[8][4];
    #pragma unroll
    for (int nb = 0; nb < 8; nb++)
        #pragma unroll
        for (int q = 0; q < 4; q++) { aU[nb][q] = 0.f; aL[nb][q] = 0.f; }

    const int it_begin = jh * 128, it_end = it_begin + 128;
    #pragma unroll 1
    for (int it = it_begin; it < it_end; ++it) {
        const int Jb = it * 4;
        #pragma unroll
        for (int kb = 0; kb < 4; kb++) {
            const int J = Jb + kb;
            // score-mma B frags for this k16 block (n = j offsets 0..7, 8..15)
            const float2 bfa = g_jext2[(size_t)(J * 16 + qr) * 4 + qc];
            const float2 bfb = g_jext2[(size_t)(J * 16 + 8 + qr) * 4 + qc];
            // scores -> f16 A fragments, no smem
            uint32_t fU0, fU1, fU2, fU3, fL0, fL1, fL2, fL3;
            score2(iaU0, iaU1, iaU2, iaU3, hU0, hU1, bfa, fU0, fU1);
            score2(iaU0, iaU1, iaU2, iaU3, hU0, hU1, bfb, fU2, fU3);
            score2(iaL0, iaL1, iaL2, iaL3, hL0, hL1, bfa, fL0, fL1);
            score2(iaL0, iaL1, iaL2, iaL3, hL0, hL1, bfb, fL2, fL3);
            // K @ U over n = 64 channels
            const uint4* bp = g_Ufrag + (size_t)(J * 4) * 32 + lane;
            #pragma unroll
            for (int nbp = 0; nbp < 4; nbp++) {
                const uint4 bb = bp[nbp * 32];
                HMMA(aU[2 * nbp],     fU0, fU1, fU2, fU3, bb.x, bb.y);
                HMMA(aU[2 * nbp + 1], fU0, fU1, fU2, fU3, bb.z, bb.w);
                HMMA(aL[2 * nbp],     fL0, fL1, fL2, fL3, bb.x, bb.y);
                HMMA(aL[2 * nbp + 1], fL0, fL1, fL2, fL3, bb.z, bb.w);
            }
        }
    }

    // epilogue: write fp32 partials
    float* P = g_part + (size_t)jh * N_PTS * C_DIM;
    #pragma unroll
    for (int nb = 0; nb < 8; nb++) {
        const int col = nb * 8 + 2 * qc;
        *(float2*)(P + (size_t)riU * C_DIM + col)       = make_float2(aU[nb][0], aU[nb][1]);
        *(float2*)(P + (size_t)(riU + 8) * C_DIM + col) = make_float2(aU[nb][2], aU[nb][3]);
        *(float2*)(P + (size_t)riL * C_DIM + col)       = make_float2(aL[nb][0], aL[nb][1]);
        *(float2*)(P + (size_t)(riL + 8) * C_DIM + col) = make_float2(aL[nb][2], aL[nb][3]);
    }
}

// ---------------- merge: out = p0 + p1 - U ----------------
__global__ void merge_kernel(const float* __restrict__ U, float* __restrict__ out) {
    int idx = blockIdx.x * blockDim.x + threadIdx.x;   // float4 index
    float4 u = ((const float4*)U)[idx];
    float4 a = ((const float4*)g_part)[idx];
    float4 b = ((const float4*)g_part)[idx + N_PTS * C_DIM / 4];
    float4 o;
    o.x = a.x + b.x - u.x;
    o.y = a.y + b.y - u.y;
    o.z = a.z + b.z - u.z;
    o.w = a.w + b.w - u.w;
    ((float4*)out)[idx] = o;
}

extern "C" void kernel_launch(void* const* d_in, const int* in_sizes, int n_in,
                              void* d_out, int out_size) {
    const float* U   = (const float*)d_in[0];
    const float* ref = (const float*)d_in[1];
    if (n_in >= 2 && in_sizes[0] == N_PTS * 5) {  // defensive metadata-order check
        U = (const float*)d_in[1];
        ref = (const float*)d_in[0];
    }
    prep_kernel<<<N_PTS / 256, 256>>>(ref);
    prepU_kernel<<<NFRAG / 256, 256>>>(U);
    lsh_main<<<512, 64>>>();
    merge_kernel<<<N_PTS * C_DIM / 4 / 256, 256>>>(U, (float*)d_out);
}

// round 9
// speedup vs baseline: 2.5837x; 1.0680x over previous
#include <cuda_runtime.h>
#include <cuda_fp16.h>
#include <cstdint>

#define N_PTS 16384
#define C_DIM 64
#define NFRAG (N_PTS / 16 * 4 * 32)   // 131072 uint4 fragments
#define JSPLIT 4

// ---------------- scratch (no allocs allowed) ----------------
__device__ uint32_t g_iext[N_PTS * 8];        // A-side feats [r0..r4,1,0,0] tf32 bits
__device__ float    g_h[N_PTS];               // exact fp32 h_i
__device__ float2   g_jext2[N_PTS * 4];       // score-mma B frags {(f0,f4),(f1,h),(f2,0),(f3,0)}
__device__ uint4    g_Ufrag[NFRAG];           // U fp16, HMMA-B fragment order
__device__ float    g_part[JSPLIT * N_PTS * C_DIM]; // split-j partials

__device__ __forceinline__ uint32_t tf32r(float v) {
    uint32_t u; asm("cvt.rna.tf32.f32 %0, %1;" : "=r"(u) : "f"(v)); return u;
}

// ---------------- prep: bilateral features ----------------
__global__ void prep_kernel(const float* __restrict__ ref) {
    int p = blockIdx.x * blockDim.x + threadIdx.x;
    if (p >= N_PTS) return;
    const float L2E = 1.4426950408889634f;
    const float S   = 1.2011224087864498f;   // sqrt(log2 e)
    float r[5]; float sq = 0.f;
    #pragma unroll
    for (int c = 0; c < 5; c++) { r[c] = ref[p * 5 + c]; sq += r[c] * r[c]; }
    float h = -0.5f * L2E * sq;
    uint32_t f[6];
    #pragma unroll
    for (int c = 0; c < 5; c++) f[c] = tf32r(r[c] * S);
    f[5] = tf32r(h);
    uint32_t* ie = g_iext + (size_t)p * 8;
    ie[0] = f[0]; ie[1] = f[1]; ie[2] = f[2]; ie[3] = f[3]; ie[4] = f[4];
    ie[5] = tf32r(1.0f); ie[6] = 0u; ie[7] = 0u;
    g_h[p] = h;
    float2* je = g_jext2 + (size_t)p * 4;
    je[0] = make_float2(__uint_as_float(f[0]), __uint_as_float(f[4]));
    je[1] = make_float2(__uint_as_float(f[1]), __uint_as_float(f[5]));
    je[2] = make_float2(__uint_as_float(f[2]), 0.f);
    je[3] = make_float2(__uint_as_float(f[3]), 0.f);
}

// ---------------- prep: U -> fp16 HMMA-B fragment order ----------------
__global__ void prepU_kernel(const float* __restrict__ U) {
    int idx = blockIdx.x * blockDim.x + threadIdx.x;
    if (idx >= NFRAG) return;
    int lane = idx & 31, nbp = (idx >> 5) & 3, J = idx >> 7;
    int qr = lane >> 2, qc = lane & 3;
    int j = J * 16 + 2 * qc;
    uint32_t rr[4];
    #pragma unroll
    for (int p = 0; p < 2; p++) {
        int c = (2 * nbp + p) * 8 + qr;
        float f0 = U[(size_t)j * C_DIM + c];
        float f1 = U[(size_t)(j + 1) * C_DIM + c];
        float f2 = U[(size_t)(j + 8) * C_DIM + c];
        float f3 = U[(size_t)(j + 9) * C_DIM + c];
        __half2 h0 = __floats2half2_rn(f0, f1);   // lo = row 2qc
        __half2 h1 = __floats2half2_rn(f2, f3);
        rr[2 * p]     = *(uint32_t*)&h0;
        rr[2 * p + 1] = *(uint32_t*)&h1;
    }
    g_Ufrag[idx] = make_uint4(rr[0], rr[1], rr[2], rr[3]);
}

// ---------------- main kernel: no smem, no barriers ----------------
__device__ __forceinline__ void score2(
    const uint32_t ia0, const uint32_t ia1, const uint32_t ia2, const uint32_t ia3,
    const float h0, const float h1, const float2 bf,
    uint32_t& w_lo, uint32_t& w_hi)
{
    uint32_t b0 = __float_as_uint(bf.x), b1 = __float_as_uint(bf.y);
    float c0 = 0.f, c1 = 0.f, c2 = 0.f, c3 = 0.f;
    asm volatile("mma.sync.aligned.m16n8k8.row.col.f32.tf32.tf32.f32 "
                 "{%0,%1,%2,%3}, {%4,%5,%6,%7}, {%8,%9}, {%0,%1,%2,%3};"
                 : "+f"(c0), "+f"(c1), "+f"(c2), "+f"(c3)
                 : "r"(ia0), "r"(ia1), "r"(ia2), "r"(ia3), "r"(b0), "r"(b1));
    float e0 = c0 + h0, e1 = c1 + h0, e2 = c2 + h1, e3 = c3 + h1;
    uint32_t plo, phi;
    asm("cvt.rn.f16x2.f32 %0, %1, %2;" : "=r"(plo) : "f"(e1), "f"(e0)); // lo=e0
    asm("cvt.rn.f16x2.f32 %0, %1, %2;" : "=r"(phi) : "f"(e3), "f"(e2));
    asm("min.f16x2 %0, %1, %2;" : "=r"(plo) : "r"(plo), "r"(0u));
    asm("min.f16x2 %0, %1, %2;" : "=r"(phi) : "r"(phi), "r"(0u));
    asm("ex2.approx.f16x2 %0, %1;" : "=r"(w_lo) : "r"(plo));
    asm("ex2.approx.f16x2 %0, %1;" : "=r"(w_hi) : "r"(phi));
}

#define HMMA(ACC, A0, A1, A2, A3, B0, B1) \
    asm volatile("mma.sync.aligned.m16n8k16.row.col.f32.f16.f16.f32 " \
                 "{%0,%1,%2,%3}, {%4,%5,%6,%7}, {%8,%9}, {%0,%1,%2,%3};" \
                 : "+f"(ACC[0]), "+f"(ACC[1]), "+f"(ACC[2]), "+f"(ACC[3]) \
                 : "r"(A0), "r"(A1), "r"(A2), "r"(A3), "r"(B0), "r"(B1))

__global__ void __launch_bounds__(64)
lsh_main(void) {
    const int lane = threadIdx.x & 31;
    const int w    = threadIdx.x >> 5;          // 0..1
    const int bid  = blockIdx.x;
    const int ib   = bid & 255;                 // i-tile (64 rows)
    const int jh   = bid >> 8;                  // j-quarter 0..3
    const int i0   = ib * 64;
    const int qr   = lane >> 2, qc = lane & 3;

    // two m16 tiles per warp: Upper rows riU(+8), Lower riL(+8)
    const int riU = i0 + w * 32 + qr;
    const int riL = riU + 16;
    const uint32_t iaU0 = g_iext[(size_t)riU * 8 + qc];
    const uint32_t iaU1 = g_iext[(size_t)(riU + 8) * 8 + qc];
    const uint32_t iaU2 = g_iext[(size_t)riU * 8 + qc + 4];
    const uint32_t iaU3 = g_iext[(size_t)(riU + 8) * 8 + qc + 4];
    const uint32_t iaL0 = g_iext[(size_t)riL * 8 + qc];
    const uint32_t iaL1 = g_iext[(size_t)(riL + 8) * 8 + qc];
    const uint32_t iaL2 = g_iext[(size_t)riL * 8 + qc + 4];
    const uint32_t iaL3 = g_iext[(size_t)(riL + 8) * 8 + qc + 4];
    const float hU0 = g_h[riU], hU1 = g_h[riU + 8];
    const float hL0 = g_h[riL], hL1 = g_h[riL + 8];

    float aU[8][4], aL[8][4];
    #pragma unroll
    for (int nb = 0; nb < 8; nb++)
        #pragma unroll
        for (int q = 0; q < 4; q++) { aU[nb][q] = 0.f; aL[nb][q] = 0.f; }

    const int J_begin = jh * (N_PTS / 16 / JSPLIT);   // 256 J-blocks per quarter
    const int J_end   = J_begin + (N_PTS / 16 / JSPLIT);

    // prefetch first block's operands
    float2 bfa = g_jext2[(size_t)(J_begin * 16 + qr) * 4 + qc];
    float2 bfb = g_jext2[(size_t)(J_begin * 16 + 8 + qr) * 4 + qc];
    const uint4* bp = g_Ufrag + (size_t)(J_begin * 4) * 32 + lane;
    uint4 bb0 = bp[0], bb1 = bp[32], bb2 = bp[64], bb3 = bp[96];

    #pragma unroll 2
    for (int J = J_begin; J < J_end; ++J) {
        // current operands
        const float2 cfa = bfa, cfb = bfb;
        const uint4 cb0 = bb0, cb1 = bb1, cb2 = bb2, cb3 = bb3;
        // prefetch next J
        if (J + 1 < J_end) {
            bfa = g_jext2[(size_t)((J + 1) * 16 + qr) * 4 + qc];
            bfb = g_jext2[(size_t)((J + 1) * 16 + 8 + qr) * 4 + qc];
            const uint4* np = g_Ufrag + (size_t)((J + 1) * 4) * 32 + lane;
            bb0 = np[0]; bb1 = np[32]; bb2 = np[64]; bb3 = np[96];
        }
        // scores -> f16 A fragments (registers only)
        uint32_t fU0, fU1, fU2, fU3, fL0, fL1, fL2, fL3;
        score2(iaU0, iaU1, iaU2, iaU3, hU0, hU1, cfa, fU0, fU1);
        score2(iaU0, iaU1, iaU2, iaU3, hU0, hU1, cfb, fU2, fU3);
        score2(iaL0, iaL1, iaL2, iaL3, hL0, hL1, cfa, fL0, fL1);
        score2(iaL0, iaL1, iaL2, iaL3, hL0, hL1, cfb, fL2, fL3);
        // K @ U over 64 channels
        HMMA(aU[0], fU0, fU1, fU2, fU3, cb0.x, cb0.y);
        HMMA(aU[1], fU0, fU1, fU2, fU3, cb0.z, cb0.w);
        HMMA(aL[0], fL0, fL1, fL2, fL3, cb0.x, cb0.y);
        HMMA(aL[1], fL0, fL1, fL2, fL3, cb0.z, cb0.w);
        HMMA(aU[2], fU0, fU1, fU2, fU3, cb1.x, cb1.y);
        HMMA(aU[3], fU0, fU1, fU2, fU3, cb1.z, cb1.w);
        HMMA(aL[2], fL0, fL1, fL2, fL3, cb1.x, cb1.y);
        HMMA(aL[3], fL0, fL1, fL2, fL3, cb1.z, cb1.w);
        HMMA(aU[4], fU0, fU1, fU2, fU3, cb2.x, cb2.y);
        HMMA(aU[5], fU0, fU1, fU2, fU3, cb2.z, cb2.w);
        HMMA(aL[4], fL0, fL1, fL2, fL3, cb2.x, cb2.y);
        HMMA(aL[5], fL0, fL1, fL2, fL3, cb2.z, cb2.w);
        HMMA(aU[6], fU0, fU1, fU2, fU3, cb3.x, cb3.y);
        HMMA(aU[7], fU0, fU1, fU2, fU3, cb3.z, cb3.w);
        HMMA(aL[6], fL0, fL1, fL2, fL3, cb3.x, cb3.y);
        HMMA(aL[7], fL0, fL1, fL2, fL3, cb3.z, cb3.w);
    }

    // epilogue: write fp32 partials
    float* P = g_part + (size_t)jh * N_PTS * C_DIM;
    #pragma unroll
    for (int nb = 0; nb < 8; nb++) {
        const int col = nb * 8 + 2 * qc;
        *(float2*)(P + (size_t)riU * C_DIM + col)       = make_float2(aU[nb][0], aU[nb][1]);
        *(float2*)(P + (size_t)(riU + 8) * C_DIM + col) = make_float2(aU[nb][2], aU[nb][3]);
        *(float2*)(P + (size_t)riL * C_DIM + col)       = make_float2(aL[nb][0], aL[nb][1]);
        *(float2*)(P + (size_t)(riL + 8) * C_DIM + col) = make_float2(aL[nb][2], aL[nb][3]);
    }
}

// ---------------- merge: out = p0+p1+p2+p3 - U ----------------
__global__ void merge_kernel(const float* __restrict__ U, float* __restrict__ out) {
    int idx = blockIdx.x * blockDim.x + threadIdx.x;   // float4 index
    float4 u = ((const float4*)U)[idx];
    float4 o = make_float4(-u.x, -u.y, -u.z, -u.w);
    #pragma unroll
    for (int s = 0; s < JSPLIT; s++) {
        float4 p = ((const float4*)g_part)[idx + (size_t)s * (N_PTS * C_DIM / 4)];
        o.x += p.x; o.y += p.y; o.z += p.z; o.w += p.w;
    }
    ((float4*)out)[idx] = o;
}

extern "C" void kernel_launch(void* const* d_in, const int* in_sizes, int n_in,
                              void* d_out, int out_size) {
    const float* U   = (const float*)d_in[0];
    const float* ref = (const float*)d_in[1];
    if (n_in >= 2 && in_sizes[0] == N_PTS * 5) {  // defensive metadata-order check
        U = (const float*)d_in[1];
        ref = (const float*)d_in[0];
    }
    prep_kernel<<<N_PTS / 256, 256>>>(ref);
    prepU_kernel<<<NFRAG / 256, 256>>>(U);
    lsh_main<<<256 * JSPLIT, 64>>>();
    merge_kernel<<<N_PTS * C_DIM / 4 / 256, 256>>>(U, (float*)d_out);
}